// round 12
// baseline (speedup 1.0000x reference)
#include <cuda_runtime.h>
#include <math.h>
#include <stdint.h>

// ---------------------------------------------------------------- constants
#define B_ROWS   1024
#define NFEAT    256
#define NSAMP    100000
#define INV_TEMP 20.0f
#define LOG2E    1.4426950408889634f
#define LN2      0.6931471805599453f
#define XSCALE   (INV_TEMP * LOG2E)      // logits computed in base-2 domain
#define CUT      40.0f                   // 2^-40 * 1e5 ~ 1e-7 relative: safe skip

#define TILE_N    128                    // samples per tile
#define TILES_TOT 782                    // ceil(100000/128)
#define NCHUNK    18
#define TPC       44                     // ceil(782/18)
#define M_CTA     128
#define NROWT     8                      // 1024/128
#define THREADS   256

// smem: A[128][260] fp32 (k-permuted) + two B k-quarter buffers [128][68] fp32
#define A_STRIDE   260
#define BQ_STRIDE  68
#define A_FLOATS   (M_CTA * A_STRIDE)                 // 33280
#define BQ_FLOATS  (TILE_N * BQ_STRIDE)               // 8704
#define SMEM_TOTAL ((A_FLOATS + 2 * BQ_FLOATS) * 4)   // 202752 bytes

// ---------------------------------------------------------------- scratch
__device__ float2 g_partials[B_ROWS * NCHUNK * 2];   // (m2, s2) per (row, chunk, n-half)
__device__ float  g_nll[B_ROWS];

// ---------------------------------------------------------------- helpers
__device__ __forceinline__ uint32_t f2tf32(float x) {
    uint32_t r; asm("cvt.rna.tf32.f32 %0, %1;" : "=r"(r) : "f"(x)); return r;
}
__device__ __forceinline__ float ex2(float x) {
    float r; asm("ex2.approx.f32 %0, %1;" : "=f"(r) : "f"(x)); return r;
}
__device__ __forceinline__ uint32_t smem_u32(const void* p) {
    uint32_t a;
    asm("{ .reg .u64 t; cvta.to.shared.u64 t, %1; cvt.u32.u64 %0, t; }" : "=r"(a) : "l"(p));
    return a;
}
__device__ __forceinline__ void mma_tf32(float* c, uint32_t a0, uint32_t a1,
                                         uint32_t a2, uint32_t a3,
                                         uint32_t b0, uint32_t b1) {
    asm volatile(
        "mma.sync.aligned.m16n8k8.row.col.f32.tf32.tf32.f32 "
        "{%0,%1,%2,%3}, {%4,%5,%6,%7}, {%8,%9}, {%0,%1,%2,%3};"
        : "+f"(c[0]), "+f"(c[1]), "+f"(c[2]), "+f"(c[3])
        : "r"(a0), "r"(a1), "r"(a2), "r"(a3), "r"(b0), "r"(b1));
}
#define CP_COMMIT() asm volatile("cp.async.commit_group;" ::: "memory")
#define CP_WAIT1()  asm volatile("cp.async.wait_group 1;"  ::: "memory")
#define CP_WAIT0()  asm volatile("cp.async.wait_group 0;"  ::: "memory")

// ---------------------------------------------------------------- B k-quarter async load
// Reads fp32 features DIRECTLY (mma truncates to tf32). OOB rows zero-filled
// via the src-size operand (0 bytes -> no access, zero fill); address clamped.
__device__ __forceinline__ void ld_quarter(const float* __restrict__ feats,
                                           float* buf, int gt, int q, int tid)
{
    const uint32_t sbase = smem_u32(buf);
    const int row0 = gt * TILE_N;
    #pragma unroll
    for (int i = 0; i < 8; i++) {
        int c  = i * THREADS + tid;             // float4 slot; 16 per 64-col row
        int rr = c >> 4;
        int cc = c & 15;
        int grow  = row0 + rr;
        int valid = (grow < NSAMP);
        int rowc  = valid ? grow : (NSAMP - 1);
        uint32_t sz = valid ? 16u : 0u;
        uint32_t sa = sbase + (uint32_t)(rr * BQ_STRIDE + cc * 4) * 4u;
        const float* ga = feats + (size_t)rowc * NFEAT + q * 64 + cc * 4;
        asm volatile("cp.async.cg.shared.global [%0], [%1], 16, %2;"
                     :: "r"(sa), "l"(ga), "r"(sz) : "memory");
    }
}

// ---------------------------------------------------------------- main fused kernel
__global__ __launch_bounds__(THREADS, 1)
void k_main(const float* __restrict__ inputs, const float* __restrict__ feats)
{
    extern __shared__ float sm[];
    float* As  = sm;                        // [128][260], k-permuted within 8-groups
    float* Bq0 = sm + A_FLOATS;             // [128][68] k-quarter buffer 0
    float* Bq1 = Bq0 + BQ_FLOATS;           // [128][68] k-quarter buffer 1

    const int tid = threadIdx.x;
    const int wid = tid >> 5;
    const int ln  = tid & 31;
    const int wm  = wid >> 1;               // m-tile: rows wm*32 .. +31 (0..3)
    const int wn  = wid & 1;                // n-half: cols wn*64 .. +63
    const int lg  = ln >> 2;                // mma groupID 0..7
    const int lt  = ln & 3;                 // mma tid-in-group 0..3

    const int r0  = blockIdx.x * M_CTA;
    const int gt0 = blockIdx.y * TPC;
    int T = TILES_TOT - gt0; if (T > TPC) T = TPC;

    // ---- prologue: first two k-quarters in flight (before A work, hides LDG)
    ld_quarter(feats, Bq0, gt0, 0, tid); CP_COMMIT();
    ld_quarter(feats, Bq1, gt0, 1, tid); CP_COMMIT();

    // ---- load A: inputs * XSCALE, tf32-rounded, k-PERMUTED within 8-groups:
    // group g holds k-order [8g+0, 8g+4, 8g+1, 8g+5, 8g+2, 8g+6, 8g+3, 8g+7]
    // so the mma pair (k, k+4) is adjacent -> LDS.64 fragment loads.
    {
        const float4* in4 = (const float4*)inputs;
        for (int i = tid; i < M_CTA * 64; i += THREADS) {
            int rr = i >> 6, cc = i & 63;
            float4 v = in4[(size_t)(r0 + rr) * 64 + cc];
            int k0 = cc * 4;                       // 8g or 8g+4
            uint32_t* dst = (uint32_t*)(As + rr * A_STRIDE + (k0 & ~7) + ((k0 & 4) ? 1 : 0));
            dst[0] = f2tf32(v.x * XSCALE);
            dst[2] = f2tf32(v.y * XSCALE);
            dst[4] = f2tf32(v.z * XSCALE);
            dst[6] = f2tf32(v.w * XSCALE);
        }
    }

    float acc[2][8][4];
    #pragma unroll
    for (int mf = 0; mf < 2; mf++)
        #pragma unroll
        for (int nf = 0; nf < 8; nf++)
            #pragma unroll
            for (int j = 0; j < 4; j++) acc[mf][nf][j] = 0.0f;

    float m[4], s[4];   // per owned row slot: r = mf*2+hh
    #pragma unroll
    for (int r = 0; r < 4; r++) { m[r] = -3.0e38f; s[r] = 0.0f; }

    const uint32_t* Ap = (const uint32_t*)As;
    const int H = 4 * T;                    // k-quarters total

    for (int h = 0; h < H; h++) {
        if (h + 1 < H) CP_WAIT1(); else CP_WAIT0();   // quarter h resident
        __syncthreads();

        const uint32_t* Bp = (const uint32_t*)((h & 1) ? Bq1 : Bq0);
        const int q = h & 3;

        #pragma unroll
        for (int ks = 0; ks < 8; ks++) {
            const int kp = q * 64 + ks * 8 + lt * 2;   // permuted (k, k+4) pair
            uint2 a0[2], a1[2];
            #pragma unroll
            for (int mf = 0; mf < 2; mf++) {
                const int rb = wm * 32 + mf * 16 + lg;
                a0[mf] = *(const uint2*)(Ap + rb * A_STRIDE + kp);
                a1[mf] = *(const uint2*)(Ap + (rb + 8) * A_STRIDE + kp);
            }
            const int kb = ks * 8 + lt;
            #pragma unroll
            for (int nf = 0; nf < 8; nf++) {
                const int nn = wn * 64 + nf * 8 + lg;
                uint32_t b0 = Bp[nn * BQ_STRIDE + kb];
                uint32_t b1 = Bp[nn * BQ_STRIDE + kb + 4];
                mma_tf32(acc[0][nf], a0[0].x, a1[0].x, a0[0].y, a1[0].y, b0, b1);
                mma_tf32(acc[1][nf], a0[1].x, a1[1].x, a0[1].y, a1[1].y, b0, b1);
            }
        }

        __syncthreads();                    // all warps done reading this buffer
        if (h + 2 < H) {                    // refill the buffer just consumed
            ld_quarter(feats, (h & 1) ? Bq1 : Bq0, gt0 + ((h + 2) >> 2), (h + 2) & 3, tid);
            CP_COMMIT();
        }

        if (q == 3) {
            // ---- tile epilogue: threshold-gated online logsumexp (base-2)
            #pragma unroll
            for (int mf = 0; mf < 2; mf++) {
                #pragma unroll
                for (int hh = 0; hh < 2; hh++) {
                    const int r = mf * 2 + hh;
                    float t0 = fmaxf(acc[mf][0][2*hh], acc[mf][0][2*hh+1]);
                    float t1 = fmaxf(acc[mf][1][2*hh], acc[mf][1][2*hh+1]);
                    float t2 = fmaxf(acc[mf][2][2*hh], acc[mf][2][2*hh+1]);
                    float t3 = fmaxf(acc[mf][3][2*hh], acc[mf][3][2*hh+1]);
                    float t4 = fmaxf(acc[mf][4][2*hh], acc[mf][4][2*hh+1]);
                    float t5 = fmaxf(acc[mf][5][2*hh], acc[mf][5][2*hh+1]);
                    float t6 = fmaxf(acc[mf][6][2*hh], acc[mf][6][2*hh+1]);
                    float t7 = fmaxf(acc[mf][7][2*hh], acc[mf][7][2*hh+1]);
                    float tmax = fmaxf(fmaxf(fmaxf(t0, t1), fmaxf(t2, t3)),
                                       fmaxf(fmaxf(t4, t5), fmaxf(t6, t7)));
                    if (tmax > m[r] - CUT) {        // rare slow path
                        float nm = fmaxf(m[r], tmax);
                        float add = 0.0f;
                        #pragma unroll
                        for (int nf = 0; nf < 8; nf++) {
                            add += ex2(acc[mf][nf][2*hh]   - nm);
                            add += ex2(acc[mf][nf][2*hh+1] - nm);
                        }
                        s[r] = s[r] * ex2(m[r] - nm) + add;
                        m[r] = nm;
                    }
                }
            }
            #pragma unroll
            for (int mf = 0; mf < 2; mf++)
                #pragma unroll
                for (int nf = 0; nf < 8; nf++)
                    #pragma unroll
                    for (int j = 0; j < 4; j++) acc[mf][nf][j] = 0.0f;
        }
    }

    // ---- merge (m,s) across the 4 lanes (lt) sharing each row; store per n-half
    #pragma unroll
    for (int r = 0; r < 4; r++) {
        float mm = m[r], ss = s[r];
        #pragma unroll
        for (int off = 1; off <= 2; off <<= 1) {
            float om = __shfl_xor_sync(0xffffffffu, mm, off);
            float os = __shfl_xor_sync(0xffffffffu, ss, off);
            float nm = fmaxf(mm, om);
            ss = ss * ex2(mm - nm) + os * ex2(om - nm);
            mm = nm;
        }
        if (lt == 0) {
            const int row = r0 + wm * 32 + (r >> 1) * 16 + (r & 1) * 8 + lg;
            g_partials[((size_t)row * NCHUNK + blockIdx.y) * 2 + wn] = make_float2(mm, ss);
        }
    }
}

// ---------------------------------------------------------------- combine + mean
__global__ void k_combine(const float* __restrict__ inputs,
                          const float* __restrict__ feats,
                          const int* __restrict__ targets)
{
    const int row = blockIdx.x;
    const int t   = threadIdx.x;

    float m = -3.0e38f, s = 0.0f;                  // base-2
    for (int c = t; c < NCHUNK * 2; c += 32) {
        float2 p = g_partials[(size_t)row * NCHUNK * 2 + c];
        float nm = fmaxf(m, p.x);
        s = s * ex2(m - nm) + p.y * ex2(p.x - nm);
        m = nm;
    }
    #pragma unroll
    for (int off = 16; off >= 1; off >>= 1) {
        float om = __shfl_xor_sync(0xffffffffu, m, off);
        float os = __shfl_xor_sync(0xffffffffu, s, off);
        float nm = fmaxf(m, om);
        s = s * ex2(m - nm) + os * ex2(om - nm);
        m = nm;
    }

    // exact target logit in fp32
    int tg = targets[row];
    tg = (tg < 0) ? 0 : ((tg >= NSAMP) ? (NSAMP - 1) : tg);
    const float* ir = inputs + (size_t)row * NFEAT;
    const float* fr = feats  + (size_t)tg  * NFEAT;
    float d = 0.0f;
    for (int k = t; k < NFEAT; k += 32) d = fmaf(ir[k], fr[k], d);
    #pragma unroll
    for (int off = 16; off >= 1; off >>= 1)
        d += __shfl_xor_sync(0xffffffffu, d, off);

    if (t == 0)
        g_nll[row] = LN2 * (m + log2f(s)) - d * INV_TEMP;
}

__global__ void k_mean(float* __restrict__ out)
{
    __shared__ float red[256];
    const int t = threadIdx.x;
    float a = 0.0f;
    for (int i = t; i < B_ROWS; i += 256) a += g_nll[i];
    red[t] = a;
    __syncthreads();
    for (int w = 128; w > 0; w >>= 1) {
        if (t < w) red[t] += red[t + w];
        __syncthreads();
    }
    if (t == 0) out[0] = red[0] * (1.0f / B_ROWS);
}

// ---------------------------------------------------------------- launch
extern "C" void kernel_launch(void* const* d_in, const int* in_sizes, int n_in,
                              void* d_out, int out_size)
{
    const float* inputs  = (const float*)d_in[0];
    const int*   targets = (const int*)d_in[1];
    const float* feats   = (const float*)d_in[2];

    cudaFuncSetAttribute(k_main, cudaFuncAttributeMaxDynamicSharedMemorySize, SMEM_TOTAL);

    dim3 grid(NROWT, NCHUNK);               // row-tile fastest -> B shared in L2
    k_main<<<grid, THREADS, SMEM_TOTAL>>>(inputs, feats);

    k_combine<<<B_ROWS, 32>>>(inputs, feats, targets);
    k_mean<<<1, 256>>>((float*)d_out);
}

// round 13
// speedup vs baseline: 1.0651x; 1.0651x over previous
#include <cuda_runtime.h>
#include <math.h>
#include <stdint.h>

// ---------------------------------------------------------------- constants
#define B_ROWS   1024
#define NFEAT    256
#define NSAMP    100000
#define INV_TEMP 20.0f
#define LOG2E    1.4426950408889634f
#define LN2      0.6931471805599453f
#define XSCALE   (INV_TEMP * LOG2E)      // logits computed in base-2 domain
#define CUT      40.0f                   // 2^-40 * 1e5 ~ 1e-7 relative: safe skip

#define TILE_N    128                    // samples per tile
#define TILES_TOT 782                    // ceil(100000/128)
#define NS_PAD    (TILES_TOT * TILE_N)   // 100096 (pad rows zeroed)
#define NCHUNK    18
#define TPC       44                     // ceil(782/18)
#define M_CTA     128
#define NROWT     8                      // 1024/128
#define THREADS   128                    // 4 warps, one per SMSP

// smem: A[128][260] fp32 + THREE swizzled B k-quarter buffers [128][64] fp32
#define A_STRIDE   260
#define A_FLOATS   (M_CTA * A_STRIDE)                  // 33280
#define BQ_FLOATS  (TILE_N * 64)                       // 8192 (stride 64, XOR swizzle)
#define NBUF       3
#define SMEM_TOTAL ((A_FLOATS + NBUF * BQ_FLOATS) * 4) // 231424 bytes <= 232448

// ---------------------------------------------------------------- scratch
__device__ float  g_ftf[(size_t)NS_PAD * NFEAT];     // tf32(.rna) features, pad rows = 0
__device__ float2 g_partials[B_ROWS * NCHUNK * 2];   // (m2, s2) per (row, chunk, n-half)
__device__ float  g_nll[B_ROWS];

// ---------------------------------------------------------------- helpers
__device__ __forceinline__ uint32_t f2tf32(float x) {
    uint32_t r; asm("cvt.rna.tf32.f32 %0, %1;" : "=r"(r) : "f"(x)); return r;
}
__device__ __forceinline__ float ex2(float x) {
    float r; asm("ex2.approx.f32 %0, %1;" : "=f"(r) : "f"(x)); return r;
}
__device__ __forceinline__ uint32_t smem_u32(const void* p) {
    uint32_t a;
    asm("{ .reg .u64 t; cvta.to.shared.u64 t, %1; cvt.u32.u64 %0, t; }" : "=r"(a) : "l"(p));
    return a;
}
__device__ __forceinline__ void mma_tf32(float* c, uint32_t a0, uint32_t a1,
                                         uint32_t a2, uint32_t a3,
                                         uint32_t b0, uint32_t b1) {
    asm volatile(
        "mma.sync.aligned.m16n8k8.row.col.f32.tf32.tf32.f32 "
        "{%0,%1,%2,%3}, {%4,%5,%6,%7}, {%8,%9}, {%0,%1,%2,%3};"
        : "+f"(c[0]), "+f"(c[1]), "+f"(c[2]), "+f"(c[3])
        : "r"(a0), "r"(a1), "r"(a2), "r"(a3), "r"(b0), "r"(b1));
}
#define CP_COMMIT() asm volatile("cp.async.commit_group;" ::: "memory")
#define CP_WAIT1()  asm volatile("cp.async.wait_group 1;"  ::: "memory")
#define CP_WAIT0()  asm volatile("cp.async.wait_group 0;"  ::: "memory")

// ---------------------------------------------------------------- convert features -> tf32 (.rna), pad rows zero
__global__ void k_convert_feats(const float* __restrict__ feats)
{
    const float4* f4 = (const float4*)feats;
    float4* o4 = (float4*)g_ftf;
    const int n4 = NS_PAD * NFEAT / 4;
    for (int i = blockIdx.x * blockDim.x + threadIdx.x; i < n4; i += gridDim.x * blockDim.x) {
        int row = i >> 6;                       // 64 float4 per row
        float4 o;
        if (row < NSAMP) {
            float4 v = f4[i];
            o.x = __uint_as_float(f2tf32(v.x));
            o.y = __uint_as_float(f2tf32(v.y));
            o.z = __uint_as_float(f2tf32(v.z));
            o.w = __uint_as_float(f2tf32(v.w));
        } else {
            o = make_float4(0.f, 0.f, 0.f, 0.f);
        }
        o4[i] = o;
    }
}

// ---------------------------------------------------------------- B k-quarter async load, XOR-swizzled
// physical float offset = row*64 + (k ^ ((row & 7) << 2)); 16B aligned, conflict-free
__device__ __forceinline__ void ld_quarter(float* buf, int Q, int tid)
{
    const int gt = Q >> 2, q = Q & 3;
    const float* src = g_ftf + (size_t)gt * TILE_N * NFEAT + q * 64;
    const uint32_t sbase = smem_u32(buf);
    #pragma unroll
    for (int i = 0; i < 16; i++) {
        int c   = i * THREADS + tid;            // float4 slot 0..2047
        int rr  = c >> 4;                       // row 0..127 (16 float4 per row)
        int cc4 = c & 15;
        uint32_t sw = (uint32_t)(rr * 64 + ((cc4 * 4) ^ ((rr & 7) << 2)));
        const float* ga = src + (size_t)rr * NFEAT + cc4 * 4;
        asm volatile("cp.async.cg.shared.global [%0], [%1], 16;"
                     :: "r"(sbase + sw * 4u), "l"(ga) : "memory");
    }
}

// ---------------------------------------------------------------- main fused kernel
__global__ __launch_bounds__(THREADS, 1)
void k_main(const float* __restrict__ inputs)
{
    extern __shared__ float sm[];
    float* As  = sm;                        // [128][260]
    float* Bqs = sm + A_FLOATS;             // 3 x [128*64] swizzled quarter buffers

    const int tid = threadIdx.x;
    const int wid = tid >> 5;
    const int ln  = tid & 31;
    const int wm  = wid >> 1;               // m-half: rows wm*64 .. +63
    const int wn  = wid & 1;                // n-half: cols wn*64 .. +63
    const int lg  = ln >> 2;                // mma groupID 0..7
    const int lt  = ln & 3;                 // mma tid-in-group 0..3

    const int r0  = blockIdx.x * M_CTA;
    const int gt0 = blockIdx.y * TPC;
    int T = TILES_TOT - gt0; if (T > TPC) T = TPC;
    const int H  = 4 * T;                   // quarters
    const int Q0 = gt0 * 4;                 // absolute first quarter

    // ---- prologue: 2 quarters in flight
    ld_quarter(Bqs + 0 * BQ_FLOATS, Q0 + 0, tid); CP_COMMIT();
    ld_quarter(Bqs + 1 * BQ_FLOATS, Q0 + 1, tid); CP_COMMIT();

    // ---- load A: inputs * XSCALE, tf32 .rna, plain padded layout (conflict-free)
    {
        const float4* in4 = (const float4*)inputs;
        for (int i = tid; i < M_CTA * 64; i += THREADS) {
            int rr = i >> 6, cc = i & 63;
            float4 v = in4[(size_t)(r0 + rr) * 64 + cc];
            uint32_t* dst = (uint32_t*)(As + rr * A_STRIDE + cc * 4);
            dst[0] = f2tf32(v.x * XSCALE);
            dst[1] = f2tf32(v.y * XSCALE);
            dst[2] = f2tf32(v.z * XSCALE);
            dst[3] = f2tf32(v.w * XSCALE);
        }
    }

    float acc[4][8][4];
    #pragma unroll
    for (int mf = 0; mf < 4; mf++)
        #pragma unroll
        for (int nf = 0; nf < 8; nf++)
            #pragma unroll
            for (int j = 0; j < 4; j++) acc[mf][nf][j] = 0.0f;

    float m[8], s[8];   // row slot r = mf*2+hh -> row wm*64 + mf*16 + hh*8 + lg
    #pragma unroll
    for (int r = 0; r < 8; r++) { m[r] = -3.0e38f; s[r] = 0.0f; }

    const uint32_t* Ap = (const uint32_t*)As;
    const uint32_t* Aw = Ap + (wm * 64 + lg) * A_STRIDE + lt;   // + q*64 + ks*8 (+4)
    const uint32_t swz = (uint32_t)(lg << 2);
    int buf = 0;                            // h % 3

    for (int h = 0; h < H; h++) {
        if (h + 1 < H) { CP_WAIT1(); } else { CP_WAIT0(); }   // quarter h resident
        __syncthreads();                     // all warps done with quarter h-1

        if (h + 2 < H) {                     // refill buffer consumed at h-1
            int nb = buf + 2; if (nb >= NBUF) nb -= NBUF;
            ld_quarter(Bqs + nb * BQ_FLOATS, Q0 + h + 2, tid);
            CP_COMMIT();
        }

        const uint32_t* Bw = (const uint32_t*)(Bqs + buf * BQ_FLOATS)
                             + (wn * 64 + lg) * 64 + lt;
        const int q = h & 3;
        const uint32_t* Aq = Aw + q * 64;

        #pragma unroll
        for (int ks = 0; ks < 8; ks++) {
            uint32_t a[4][4];
            #pragma unroll
            for (int mf = 0; mf < 4; mf++) {
                const uint32_t* Am = Aq + mf * 16 * A_STRIDE + ks * 8;
                a[mf][0] = Am[0];
                a[mf][1] = Am[8 * A_STRIDE];
                a[mf][2] = Am[4];
                a[mf][3] = Am[8 * A_STRIDE + 4];
            }
            const int k0 = (ks * 8)     ^ (int)swz;   // lt already folded into Bw
            const int k1 = (ks * 8 + 4) ^ (int)swz;
            #pragma unroll
            for (int nf = 0; nf < 8; nf++) {
                uint32_t b0 = Bw[nf * 512 + k0];
                uint32_t b1 = Bw[nf * 512 + k1];
                #pragma unroll
                for (int mf = 0; mf < 4; mf++)
                    mma_tf32(acc[mf][nf], a[mf][0], a[mf][1], a[mf][2], a[mf][3], b0, b1);
            }
        }

        buf++; if (buf >= NBUF) buf = 0;

        if (q == 3) {
            // ---- tile epilogue: threshold-gated online logsumexp (base-2)
            #pragma unroll
            for (int mf = 0; mf < 4; mf++) {
                #pragma unroll
                for (int hh = 0; hh < 2; hh++) {
                    const int r = mf * 2 + hh;
                    float t0 = fmaxf(acc[mf][0][2*hh], acc[mf][0][2*hh+1]);
                    float t1 = fmaxf(acc[mf][1][2*hh], acc[mf][1][2*hh+1]);
                    float t2 = fmaxf(acc[mf][2][2*hh], acc[mf][2][2*hh+1]);
                    float t3 = fmaxf(acc[mf][3][2*hh], acc[mf][3][2*hh+1]);
                    float t4 = fmaxf(acc[mf][4][2*hh], acc[mf][4][2*hh+1]);
                    float t5 = fmaxf(acc[mf][5][2*hh], acc[mf][5][2*hh+1]);
                    float t6 = fmaxf(acc[mf][6][2*hh], acc[mf][6][2*hh+1]);
                    float t7 = fmaxf(acc[mf][7][2*hh], acc[mf][7][2*hh+1]);
                    float tmax = fmaxf(fmaxf(fmaxf(t0, t1), fmaxf(t2, t3)),
                                       fmaxf(fmaxf(t4, t5), fmaxf(t6, t7)));
                    if (tmax > m[r] - CUT) {        // rare slow path
                        float nm = fmaxf(m[r], tmax);
                        float add = 0.0f;
                        #pragma unroll
                        for (int nf = 0; nf < 8; nf++) {
                            add += ex2(acc[mf][nf][2*hh]   - nm);
                            add += ex2(acc[mf][nf][2*hh+1] - nm);
                        }
                        s[r] = s[r] * ex2(m[r] - nm) + add;
                        m[r] = nm;
                    }
                }
            }
            #pragma unroll
            for (int mf = 0; mf < 4; mf++)
                #pragma unroll
                for (int nf = 0; nf < 8; nf++)
                    #pragma unroll
                    for (int j = 0; j < 4; j++) acc[mf][nf][j] = 0.0f;
        }
    }

    // ---- merge (m,s) across the 4 lanes (lt) sharing each row; store per n-half
    #pragma unroll
    for (int r = 0; r < 8; r++) {
        float mm = m[r], ss = s[r];
        #pragma unroll
        for (int off = 1; off <= 2; off <<= 1) {
            float om = __shfl_xor_sync(0xffffffffu, mm, off);
            float os = __shfl_xor_sync(0xffffffffu, ss, off);
            float nm = fmaxf(mm, om);
            ss = ss * ex2(mm - nm) + os * ex2(om - nm);
            mm = nm;
        }
        if (lt == 0) {
            const int row = r0 + wm * 64 + (r >> 1) * 16 + (r & 1) * 8 + lg;
            g_partials[((size_t)row * NCHUNK + blockIdx.y) * 2 + wn] = make_float2(mm, ss);
        }
    }
}

// ---------------------------------------------------------------- combine + mean
__global__ void k_combine(const float* __restrict__ inputs,
                          const float* __restrict__ feats,
                          const int* __restrict__ targets)
{
    const int row = blockIdx.x;
    const int t   = threadIdx.x;

    float m = -3.0e38f, s = 0.0f;                  // base-2
    for (int c = t; c < NCHUNK * 2; c += 32) {
        float2 p = g_partials[(size_t)row * NCHUNK * 2 + c];
        float nm = fmaxf(m, p.x);
        s = s * ex2(m - nm) + p.y * ex2(p.x - nm);
        m = nm;
    }
    #pragma unroll
    for (int off = 16; off >= 1; off >>= 1) {
        float om = __shfl_xor_sync(0xffffffffu, m, off);
        float os = __shfl_xor_sync(0xffffffffu, s, off);
        float nm = fmaxf(m, om);
        s = s * ex2(m - nm) + os * ex2(om - nm);
        m = nm;
    }

    // exact target logit in fp32
    int tg = targets[row];
    tg = (tg < 0) ? 0 : ((tg >= NSAMP) ? (NSAMP - 1) : tg);
    const float* ir = inputs + (size_t)row * NFEAT;
    const float* fr = feats  + (size_t)tg  * NFEAT;
    float d = 0.0f;
    for (int k = t; k < NFEAT; k += 32) d = fmaf(ir[k], fr[k], d);
    #pragma unroll
    for (int off = 16; off >= 1; off >>= 1)
        d += __shfl_xor_sync(0xffffffffu, d, off);

    if (t == 0)
        g_nll[row] = LN2 * (m + log2f(s)) - d * INV_TEMP;
}

__global__ void k_mean(float* __restrict__ out)
{
    __shared__ float red[256];
    const int t = threadIdx.x;
    float a = 0.0f;
    for (int i = t; i < B_ROWS; i += 256) a += g_nll[i];
    red[t] = a;
    __syncthreads();
    for (int w = 128; w > 0; w >>= 1) {
        if (t < w) red[t] += red[t + w];
        __syncthreads();
    }
    if (t == 0) out[0] = red[0] * (1.0f / B_ROWS);
}

// ---------------------------------------------------------------- launch
extern "C" void kernel_launch(void* const* d_in, const int* in_sizes, int n_in,
                              void* d_out, int out_size)
{
    const float* inputs  = (const float*)d_in[0];
    const int*   targets = (const int*)d_in[1];
    const float* feats   = (const float*)d_in[2];

    cudaFuncSetAttribute(k_main, cudaFuncAttributeMaxDynamicSharedMemorySize, SMEM_TOTAL);

    k_convert_feats<<<2048, 256>>>(feats);

    dim3 grid(NROWT, NCHUNK);               // row-tile fastest -> B shared in L2
    k_main<<<grid, THREADS, SMEM_TOTAL>>>(inputs);

    k_combine<<<B_ROWS, 32>>>(inputs, feats, targets);
    k_mean<<<1, 256>>>((float*)d_out);
}